// round 1
// baseline (speedup 1.0000x reference)
#include <cuda_runtime.h>
#include <cstdint>
#include <cstddef>

#define BB 8
#define NN 2048
#define DD 128

// Scratch (allocation-free rule: __device__ globals)
__device__ float g_y [BB * NN * DD];
__device__ float g_x0[BB * NN * DD];
__device__ float g_x1[BB * NN * DD];
__device__ float g_invden[BB * NN];

typedef unsigned long long u64;

__device__ __forceinline__ void fma2(u64 &c, u64 a, u64 b) {
    // packed fp32x2 FMA (FFMA2) — 2x fp32 throughput vs scalar FFMA on sm_103a
    asm("fma.rn.f32x2 %0, %1, %2, %0;" : "+l"(c) : "l"(a), "l"(b));
}
__device__ __forceinline__ u64 pack2(float lo, float hi) {
    u64 r; asm("mov.b64 %0, {%1, %2};" : "=l"(r) : "f"(lo), "f"(hi)); return r;
}
__device__ __forceinline__ float2 unpack2(u64 v) {
    float2 r; asm("mov.b64 {%0, %1}, %2;" : "=f"(r.x), "=f"(r.y) : "l"(v)); return r;
}

// One kernel template for both GEMMs:
//   AX path  : KTOT=2048, lda=2048, grid=(16, 8), optional DENOM (layer 0 computes invden)
//   XW path  : KTOT=128,  lda=128,  grid=(128,1), EPI (bias + *invden + relu)
// CTA tile 128x128, 256 threads, 8x8 per thread, BK=32, reg-prefetch double buffer.
template<int KTOT, bool DENOM, bool EPI>
__global__ __launch_bounds__(256, 1) void gcn_gemm(
    const float* __restrict__ Aptr, size_t strideA, int lda,
    const float* __restrict__ Bptr, size_t strideB,
    const float* __restrict__ bias,
    const float* __restrict__ invden,
    float* __restrict__ invden_out,
    float* __restrict__ Outp, size_t strideOut)
{
    __shared__ __align__(16) float As[32][132];  // pad 4 floats: keeps 16B align (528B row), fewer STS conflicts
    __shared__ __align__(16) float Bs[32][128];

    const float* Ab = Aptr + (size_t)blockIdx.y * strideA;
    const float* Bb = Bptr + (size_t)blockIdx.y * strideB;
    float*       Ob = Outp + (size_t)blockIdx.y * strideOut;

    const int tid = threadIdx.x;
    const int m0  = blockIdx.x * 128;

    // A loader: each thread loads 4x float4 along k, rows mA + 32*i
    const int mA = tid >> 3;
    const int kA = (tid & 7) << 2;
    // B loader: each thread loads 4x float4 along n, rows (k) kB + 8*i
    const int kB = tid >> 5;
    const int nB = (tid & 31) << 2;

    const int tx = tid & 15, ty = tid >> 4;
    const int r0 = (ty << 2), r1 = (ty << 2) + 64;
    const int c0 = (tx << 2), c1 = (tx << 2) + 64;

    u64 acc[8][4];
    #pragma unroll
    for (int i = 0; i < 8; i++)
        #pragma unroll
        for (int j = 0; j < 4; j++) acc[i][j] = 0ull;

    float rowsum[4] = {0.f, 0.f, 0.f, 0.f};

    float4 pa[4], pb[4];

    // prologue: load tile k0 = 0 into registers
    #pragma unroll
    for (int i = 0; i < 4; i++)
        pa[i] = *reinterpret_cast<const float4*>(Ab + (size_t)(m0 + mA + 32 * i) * lda + kA);
    #pragma unroll
    for (int i = 0; i < 4; i++)
        pb[i] = *reinterpret_cast<const float4*>(Bb + (size_t)(kB + 8 * i) * DD + nB);

    for (int k0 = 0;;) {
        if (DENOM) {
            #pragma unroll
            for (int i = 0; i < 4; i++)
                rowsum[i] += pa[i].x + pa[i].y + pa[i].z + pa[i].w;
        }
        // regs -> smem (A stored transposed: As[k][m])
        #pragma unroll
        for (int i = 0; i < 4; i++) {
            As[kA + 0][mA + 32 * i] = pa[i].x;
            As[kA + 1][mA + 32 * i] = pa[i].y;
            As[kA + 2][mA + 32 * i] = pa[i].z;
            As[kA + 3][mA + 32 * i] = pa[i].w;
        }
        #pragma unroll
        for (int i = 0; i < 4; i++)
            *reinterpret_cast<float4*>(&Bs[kB + 8 * i][nB]) = pb[i];
        __syncthreads();

        k0 += 32;
        const bool more = (k0 < KTOT);
        if (more) {  // prefetch next tile while computing current
            #pragma unroll
            for (int i = 0; i < 4; i++)
                pa[i] = *reinterpret_cast<const float4*>(Ab + (size_t)(m0 + mA + 32 * i) * lda + k0 + kA);
            #pragma unroll
            for (int i = 0; i < 4; i++)
                pb[i] = *reinterpret_cast<const float4*>(Bb + (size_t)(k0 + kB + 8 * i) * DD + nB);
        }

        #pragma unroll
        for (int k = 0; k < 32; k++) {
            float4 a0 = *reinterpret_cast<const float4*>(&As[k][r0]);
            float4 a1 = *reinterpret_cast<const float4*>(&As[k][r1]);
            float4 b0 = *reinterpret_cast<const float4*>(&Bs[k][c0]);
            float4 b1 = *reinterpret_cast<const float4*>(&Bs[k][c1]);
            u64 bp[4] = { pack2(b0.x, b0.y), pack2(b0.z, b0.w),
                          pack2(b1.x, b1.y), pack2(b1.z, b1.w) };
            float ar[8] = {a0.x, a0.y, a0.z, a0.w, a1.x, a1.y, a1.z, a1.w};
            #pragma unroll
            for (int i = 0; i < 8; i++) {
                u64 ap = pack2(ar[i], ar[i]);
                #pragma unroll
                for (int j = 0; j < 4; j++) fma2(acc[i][j], ap, bp[j]);
            }
        }
        if (!more) break;
        __syncthreads();
    }

    // epilogue
    float4 bia0, bia1;
    if (EPI) {
        bia0 = *reinterpret_cast<const float4*>(bias + c0);
        bia1 = *reinterpret_cast<const float4*>(bias + c1);
    }
    #pragma unroll
    for (int i = 0; i < 8; i++) {
        const int r = (i < 4) ? (r0 + i) : (r1 + i - 4);
        float2 p0 = unpack2(acc[i][0]);
        float2 p1 = unpack2(acc[i][1]);
        float2 p2 = unpack2(acc[i][2]);
        float2 p3 = unpack2(acc[i][3]);
        float* orow = Ob + (size_t)(m0 + r) * DD;
        if (EPI) {
            const float id = invden[m0 + r];
            float4 o0, o1;
            o0.x = fmaxf((p0.x + bia0.x) * id, 0.f);
            o0.y = fmaxf((p0.y + bia0.y) * id, 0.f);
            o0.z = fmaxf((p1.x + bia0.z) * id, 0.f);
            o0.w = fmaxf((p1.y + bia0.w) * id, 0.f);
            o1.x = fmaxf((p2.x + bia1.x) * id, 0.f);
            o1.y = fmaxf((p2.y + bia1.y) * id, 0.f);
            o1.z = fmaxf((p3.x + bia1.z) * id, 0.f);
            o1.w = fmaxf((p3.y + bia1.w) * id, 0.f);
            *reinterpret_cast<float4*>(orow + c0) = o0;
            *reinterpret_cast<float4*>(orow + c1) = o1;
        } else {
            float4 o0 = {p0.x, p0.y, p1.x, p1.y};
            float4 o1 = {p2.x, p2.y, p3.x, p3.y};
            *reinterpret_cast<float4*>(orow + c0) = o0;
            *reinterpret_cast<float4*>(orow + c1) = o1;
        }
    }

    if (DENOM) {
        // 8 threads (tid&7 = 0..7) share each row mA(+32i); reduce within 8-lane groups
        #pragma unroll
        for (int i = 0; i < 4; i++) {
            float s = rowsum[i];
            s += __shfl_xor_sync(0xffffffffu, s, 4);
            s += __shfl_xor_sync(0xffffffffu, s, 2);
            s += __shfl_xor_sync(0xffffffffu, s, 1);
            if ((tid & 7) == 0)
                invden_out[(size_t)blockIdx.y * NN + m0 + mA + 32 * i] = 1.f / (s + 1.f);
        }
    }
}

extern "C" void kernel_launch(void* const* d_in, const int* in_sizes, int n_in,
                              void* d_out, int out_size)
{
    // Robustly identify inputs by element count (all distinct)
    const float *inputs = nullptr, *adj = nullptr, *W = nullptr, *bias = nullptr;
    for (int i = 0; i < n_in; i++) {
        const long long s = in_sizes[i];
        if      (s == (long long)BB * NN * DD) inputs = (const float*)d_in[i];
        else if (s == (long long)BB * NN * NN) adj    = (const float*)d_in[i];
        else if (s == 3LL * DD * DD)           W      = (const float*)d_in[i];
        else if (s == 3LL * DD)                bias   = (const float*)d_in[i];
    }
    float* out = (float*)d_out;

    float *y, *x0, *x1, *invd;
    cudaGetSymbolAddress((void**)&y,    g_y);
    cudaGetSymbolAddress((void**)&x0,   g_x0);
    cudaGetSymbolAddress((void**)&x1,   g_x1);
    cudaGetSymbolAddress((void**)&invd, g_invden);

    const dim3 blk(256);
    const dim3 gAX(NN / 128, BB);
    const dim3 gXW((BB * NN) / 128, 1);
    const size_t sAdj = (size_t)NN * NN;
    const size_t sX   = (size_t)NN * DD;

    // layer 0 (also computes invden from adj row sums, fused into the A loads)
    gcn_gemm<NN, true,  false><<<gAX, blk>>>(adj, sAdj, NN, inputs, sX, nullptr, nullptr, invd, y, sX);
    gcn_gemm<DD, false, true ><<<gXW, blk>>>(y, 0, DD, W,              0, bias,          invd, nullptr, x0, 0);
    // layer 1
    gcn_gemm<NN, false, false><<<gAX, blk>>>(adj, sAdj, NN, x0, sX, nullptr, nullptr, nullptr, y, sX);
    gcn_gemm<DD, false, true ><<<gXW, blk>>>(y, 0, DD, W + DD * DD,    0, bias + DD,     invd, nullptr, x1, 0);
    // layer 2
    gcn_gemm<NN, false, false><<<gAX, blk>>>(adj, sAdj, NN, x1, sX, nullptr, nullptr, nullptr, y, sX);
    gcn_gemm<DD, false, true ><<<gXW, blk>>>(y, 0, DD, W + 2 * DD * DD, 0, bias + 2 * DD, invd, nullptr, out, 0);
}